// round 15
// baseline (speedup 1.0000x reference)
#include <cuda_runtime.h>
#include <math.h>

#define NM      64
#define A_DIM   8400
#define E_DIM   128
#define NHEAD   4
#define HDIM    32
#define HWSZ    25600      // 160*160
#define LN_EPS  1e-5f
#define LOG2E   1.4426950408889634f
#define TABN    1024
#define XMIN    -10.0f
#define XMAX    10.0f

#define N_POOLB   320            // pool role: 1280 float4 each (5 blocks/module, exact)
#define N_TABB    16             // table role: 64 nodes each (4 threads/node)
#define GRID_A    (N_POOLB + N_TABB)   // 336
#define TPB       256

#define APPLY_BLOCKS 350
#define APPLY_TPB    384         // 350*384 = 134400 float4 exactly

#define COEFF_LINES 16800        // 537600 floats * 4B / 128B
#define LINES_PER_BLOCK 53       // ceil(16800/320)

// ---------------- device scratch (no allocation allowed) ----------------
__device__ float        g_partial[N_POOLB];
__device__ float4       g_AB[NHEAD * NM];   // (A1,A2,A3,W); A* pre-scaled log2e*scale
__device__ float        g_qstat[3];         // {Vw, 2*Cwb, Vb+eps} for queries
__device__ __align__(16) float2 g_G2[TABN]; // (G[i], G[i+1]) pairs — gate folded in
__device__ unsigned int g_sync[2];          // {pool_done, tab_done}; zero-init

__device__ __forceinline__ float fast_ex2(float x) {
    float y; asm("ex2.approx.f32 %0, %1;" : "=f"(y) : "f"(x)); return y;
}

__device__ __forceinline__ void spin_until(unsigned int* ctr, unsigned int target) {
    while (*((volatile unsigned int*)ctr) < target) __nanosleep(64);
    __threadfence();   // acquire
}

// one head's softmax contribution: ws/se over 64 modules (r precomputed)
__device__ __forceinline__ float eval_head(float x, float r, const float4* __restrict__ ABh)
{
    float mx = -1e30f;
    #pragma unroll 8
    for (int m = 0; m < NM; m++) {
        float4 ab = ABh[m];
        float s = fmaf(r, fmaf(x, ab.x, ab.y), ab.z);
        mx = fmaxf(mx, s);
    }
    float se = 0.f, ws = 0.f;
    #pragma unroll 8
    for (int m = 0; m < NM; m++) {
        float4 ab = ABh[m];
        float s = fmaf(r, fmaf(x, ab.x, ab.y), ab.z);
        float e = fast_ex2(s - mx);
        se += e;
        ws = fmaf(e, ab.w, ws);
    }
    return __fdividef(ws, se);
}

// cold fallback for |x| > 10: full F + gate from global coeffs
__device__ __noinline__ float eval_G_cold(float x, float gw0, float gw1, float gbv, float ob)
{
    float qa = g_qstat[0], qb2 = g_qstat[1], qc = g_qstat[2];
    float r = rsqrtf(fmaf(x, fmaf(qa, x, qb2), qc));
    float F = ob;
    #pragma unroll
    for (int h = 0; h < NHEAD; h++)
        F += eval_head(x, r, g_AB + h * NM);
    float z = fmaf(gw1, F, fmaf(gw0, x, gbv));
    float g = __fdividef(1.0f, 1.0f + fast_ex2(z));
    return fmaf(g, F - x, x);
}

// =========== kernel A: pool (+coeff L2-prefetch) + coefficients + G-table ===========
__global__ __launch_bounds__(TPB) void pooltab_kernel(
    const float* __restrict__ proto, const float* __restrict__ coeff,
    const float* __restrict__ qw, const float* __restrict__ qb,
    const float* __restrict__ qg, const float* __restrict__ qbeta,
    const float* __restrict__ kw, const float* __restrict__ kb,
    const float* __restrict__ kg, const float* __restrict__ kbeta,
    const float* __restrict__ vw, const float* __restrict__ vb,
    const float* __restrict__ vg, const float* __restrict__ vbeta,
    const float* __restrict__ outw, const float* __restrict__ outb,
    const float* __restrict__ gatew, const float* __restrict__ gateb)
{
    const int bid = blockIdx.x;
    const int t   = threadIdx.x;

    // ======================= POOL role =======================
    if (bid < N_POOLB) {
        __shared__ float s_red[8];
        const float4* p4 = reinterpret_cast<const float4*>(proto) + (size_t)bid * 1280;
        float4 v0 = p4[t];
        float4 v1 = p4[t + 256];
        float4 v2 = p4[t + 512];
        float4 v3 = p4[t + 768];
        float4 v4 = p4[t + 1024];

        // fire-and-forget: warm L2 with this block's slice of coeff
        if (t < LINES_PER_BLOCK) {
            int line = bid * LINES_PER_BLOCK + t;
            if (line < COEFF_LINES) {
                const char* cp = reinterpret_cast<const char*>(coeff) + (size_t)line * 128;
                asm volatile("prefetch.global.L2 [%0];" :: "l"(cp));
            }
        }

        float s0 = (v0.x + v0.y) + (v0.z + v0.w);
        float s1 = (v1.x + v1.y) + (v1.z + v1.w);
        float s2 = (v2.x + v2.y) + (v2.z + v2.w);
        float s3 = (v3.x + v3.y) + (v3.z + v3.w);
        float s4 = (v4.x + v4.y) + (v4.z + v4.w);
        float sum = ((s0 + s1) + (s2 + s3)) + s4;
        #pragma unroll
        for (int off = 16; off; off >>= 1) sum += __shfl_down_sync(0xffffffffu, sum, off);
        if ((t & 31) == 0) s_red[t >> 5] = sum;
        __syncthreads();
        if (t == 0) {
            float v = 0.f;
            #pragma unroll
            for (int w2 = 0; w2 < 8; w2++) v += s_red[w2];
            g_partial[bid] = v;
            __threadfence();   // release
            atomicAdd(&g_sync[0], 1u);
        }
        return;
    }

    // ======================= TABLE role =======================
    {
        const int tb = bid - N_POOLB;        // 0..15
        __shared__ float  s_pooled[NM];
        __shared__ float  s_stats[15];
        __shared__ float4 s_k[E_DIM];
        __shared__ float4 s_v[E_DIM];
        __shared__ float4 s_q[E_DIM];
        __shared__ float  s_ow[E_DIM];
        __shared__ float4 sAB[NHEAD * NM];

        // phase A (overlaps pool): stage params + moments
        if (t < E_DIM) {
            s_k[t] = make_float4(kw[t], kb[t], kg[t], kbeta[t]);
            s_v[t] = make_float4(vw[t], vb[t], vg[t], vbeta[t]);
            s_q[t] = make_float4(qw[t], qb[t], qg[t], qbeta[t]);
            s_ow[t] = outw[t];
        }
        if (t >= 64 && t < 96) {             // warp 2: moment sums
            int lane = t & 31;
            float acc[15];
            #pragma unroll
            for (int i = 0; i < 15; i++) acc[i] = 0.f;
            #pragma unroll
            for (int rep = 0; rep < 4; rep++) {
                int e = lane + rep * 32;
                float a, b;
                a = qw[e]; b = qb[e];
                acc[0] += a; acc[1] += b; acc[2] += a*a; acc[3] += a*b; acc[4] += b*b;
                a = kw[e]; b = kb[e];
                acc[5] += a; acc[6] += b; acc[7] += a*a; acc[8] += a*b; acc[9] += b*b;
                a = vw[e]; b = vb[e];
                acc[10] += a; acc[11] += b; acc[12] += a*a; acc[13] += a*b; acc[14] += b*b;
            }
            #pragma unroll
            for (int off = 16; off; off >>= 1)
                #pragma unroll
                for (int i = 0; i < 15; i++) acc[i] += __shfl_down_sync(0xffffffffu, acc[i], off);
            if (lane == 0) {
                const float inv = 1.0f / (float)E_DIM;
                #pragma unroll
                for (int gi = 0; gi < 3; gi++) {
                    float mw = acc[gi*5+0] * inv;
                    float mb = acc[gi*5+1] * inv;
                    s_stats[gi*5+0] = mw;
                    s_stats[gi*5+1] = mb;
                    s_stats[gi*5+2] = acc[gi*5+2] * inv - mw*mw;
                    s_stats[gi*5+3] = acc[gi*5+3] * inv - mw*mb;
                    s_stats[gi*5+4] = acc[gi*5+4] * inv - mb*mb;
                }
            }
        }

        // wait for pool
        if (t == 0) spin_until(&g_sync[0], N_POOLB);
        __syncthreads();

        if (t < NM) {
            float s = 0.f;
            #pragma unroll
            for (int j = 0; j < 5; j++) s += g_partial[t * 5 + j];
            s_pooled[t] = s * (1.0f / (float)HWSZ);
        }
        __syncthreads();

        float qa  = s_stats[2];
        float qb2 = 2.0f * s_stats[3];
        float qc  = s_stats[4] + LN_EPS;
        if (tb == 0 && t == 0) {
            g_qstat[0] = qa; g_qstat[1] = qb2; g_qstat[2] = qc;
        }

        // coefficients: thread t -> (head, module) entry t (256 exact)
        {
            float mqw = s_stats[0],  mqb = s_stats[1];
            float mkw = s_stats[5],  mkb = s_stats[6];
            float Vkw = s_stats[7],  Ckwb = s_stats[8],  Vkb = s_stats[9];
            float mvw = s_stats[10], mvb = s_stats[11];
            float Vvw = s_stats[12], Cvwb = s_stats[13], Vvb = s_stats[14];
            const float cscale = rsqrtf((float)HDIM) * LOG2E;

            int h = t >> 6, m = t & 63;
            float p = s_pooled[m];
            float rk = rsqrtf(p * p * Vkw + 2.0f * p * Ckwb + Vkb + LN_EPS);
            float rv = rsqrtf(p * p * Vvw + 2.0f * p * Cvwb + Vvb + LN_EPS);

            float a1 = 0.f, a2 = 0.f, a3 = 0.f, w = 0.f;
            #pragma unroll 8
            for (int j = 0; j < HDIM; j++) {
                int e = h * HDIM + j;
                float4 kk = s_k[e];
                float4 vv = s_v[e];
                float4 qq = s_q[e];
                float ke = ((kk.x - mkw) * p + (kk.y - mkb)) * rk * kk.z + kk.w;
                float ve = ((vv.x - mvw) * p + (vv.y - mvb)) * rv * vv.z + vv.w;
                float uq = (qq.x - mqw) * qq.z;
                float tq = (qq.y - mqb) * qq.z;
                a1 = fmaf(uq, ke, a1);
                a2 = fmaf(tq, ke, a2);
                a3 = fmaf(qq.w, ke, a3);
                w  = fmaf(ve, s_ow[e], w);
            }
            float4 out4 = make_float4(a1 * cscale, a2 * cscale, a3 * cscale, w);
            sAB[t] = out4;
            if (tb == 0) g_AB[t] = out4;
        }
        __syncthreads();

        // G-table: 4 threads/node (one head each), shfl-combine, gate folded
        const float hstep = (XMAX - XMIN) / (float)(TABN - 1);
        float ob  = outb[0];
        float gw0 = __ldg(gatew)     * -LOG2E;
        float gw1 = __ldg(gatew + 1) * -LOG2E;
        float gbv = __ldg(gateb)     * -LOG2E;
        int node = tb * 64 + (t >> 2);       // 16 blocks * 64 = 1024
        int hh   = t & 3;
        float x  = XMIN + (float)node * hstep;
        float r  = rsqrtf(fmaf(x, fmaf(qa, x, qb2), qc));
        float part = eval_head(x, r, sAB + (hh << 6));
        part += __shfl_xor_sync(0xffffffffu, part, 1);
        part += __shfl_xor_sync(0xffffffffu, part, 2);
        if (hh == 0) {
            float F = part + ob;
            float z = fmaf(gw1, F, fmaf(gw0, x, gbv));
            float g = __fdividef(1.0f, 1.0f + fast_ex2(z));
            float G = fmaf(g, F - x, x);
            g_G2[node].x = G;
            if (node > 0) g_G2[node - 1].y = G;
        }
        __threadfence();
        __syncthreads();
        // last tab block resets counters (all tab blocks have passed the spin)
        if (t == 0) {
            unsigned int old = atomicAdd(&g_sync[1], 1u);
            if (old == (unsigned int)(N_TABB - 1)) {
                atomicExch(&g_sync[0], 0u);
                atomicExch(&g_sync[1], 0u);
            }
        }
    }
}

// =========== kernel B: apply (direct gather; coeff warm in L2) ===========
__global__ __launch_bounds__(APPLY_TPB) void apply_kernel(
    const float* __restrict__ coeff, float* __restrict__ out,
    const float* __restrict__ gatew, const float* __restrict__ gateb,
    const float* __restrict__ outb)
{
    int tid = blockIdx.x * APPLY_TPB + threadIdx.x;   // one float4 each, exact
    const float4* cin = reinterpret_cast<const float4*>(coeff);
    float4* cout = reinterpret_cast<float4*>(out);
    float gw0 = __ldg(gatew)     * -LOG2E;
    float gw1 = __ldg(gatew + 1) * -LOG2E;
    float gbv = __ldg(gateb)     * -LOG2E;
    float ob  = __ldg(outb);

    const float INVH = (float)(TABN - 1) / (XMAX - XMIN);
    const float BIAS = -XMIN * INVH;

    float4 xv = cin[tid];
    float xin[4] = {xv.x, xv.y, xv.z, xv.w};

    // issue all 4 table gathers up front (independent -> MLP)
    float2 p[4];
    float fpos[4];
    bool inr[4];
    #pragma unroll
    for (int j = 0; j < 4; j++) {
        float x = xin[j];
        inr[j] = (x >= XMIN) && (x <= XMAX);
        float tpos = fmaf(x, INVH, BIAS);
        int q0 = __float2int_rd(tpos);
        q0 = (q0 < 0) ? 0 : ((q0 > TABN - 2) ? TABN - 2 : q0);
        fpos[j] = tpos - (float)q0;
        p[j] = g_G2[q0];
    }

    float res[4];
    #pragma unroll
    for (int j = 0; j < 4; j++) {
        float x = xin[j];
        res[j] = inr[j] ? fmaf(fpos[j], p[j].y - p[j].x, p[j].x)
                        : eval_G_cold(x, gw0, gw1, gbv, ob);
    }
    cout[tid] = make_float4(res[0], res[1], res[2], res[3]);
}

// ---------------- launch ----------------
extern "C" void kernel_launch(void* const* d_in, const int* in_sizes, int n_in,
                              void* d_out, int out_size) {
    (void)in_sizes; (void)n_in; (void)out_size;
    const float* coeff = (const float*)d_in[0];
    const float* proto = (const float*)d_in[1];
    const float* qw    = (const float*)d_in[2];
    const float* qb    = (const float*)d_in[3];
    const float* qg    = (const float*)d_in[4];
    const float* qbeta = (const float*)d_in[5];
    const float* kw    = (const float*)d_in[6];
    const float* kb    = (const float*)d_in[7];
    const float* kg    = (const float*)d_in[8];
    const float* kbeta = (const float*)d_in[9];
    const float* vw    = (const float*)d_in[10];
    const float* vb    = (const float*)d_in[11];
    const float* vg    = (const float*)d_in[12];
    const float* vbeta = (const float*)d_in[13];
    const float* outw  = (const float*)d_in[14];
    const float* outb  = (const float*)d_in[15];
    const float* gatew = (const float*)d_in[16];
    const float* gateb = (const float*)d_in[17];
    float* out = (float*)d_out;

    pooltab_kernel<<<GRID_A, TPB>>>(proto, coeff,
                                    qw, qb, qg, qbeta, kw, kb, kg, kbeta,
                                    vw, vb, vg, vbeta, outw, outb,
                                    gatew, gateb);
    apply_kernel<<<APPLY_BLOCKS, APPLY_TPB>>>(coeff, out, gatew, gateb, outb);
}

// round 16
// speedup vs baseline: 1.0514x; 1.0514x over previous
#include <cuda_runtime.h>
#include <math.h>

#define NM      64
#define A_DIM   8400
#define E_DIM   128
#define NHEAD   4
#define HDIM    32
#define HWSZ    25600      // 160*160
#define LN_EPS  1e-5f
#define LOG2E   1.4426950408889634f
#define TABN    8192
#define XMIN    -10.0f
#define XMAX    10.0f

#define POOL_BLOCKS 320          // 1280 float4 each, 5 blocks per module (exact)
#define POOL_TPB    256

#define TA_BLOCKS   350
#define TA_TPB      384          // 350*384 = 134400 float4 exactly
#define N_TABB      64           // blocks 0..63 build 128 nodes each (2 thr/node)

// ---------------- device scratch (no allocation allowed) ----------------
__device__ float        g_partial[POOL_BLOCKS];
__device__ float4       g_AB[NHEAD * NM];   // (A1,A2,A3,W); A* pre-scaled log2e*scale
__device__ float        g_qstat[3];         // {Vw, 2*Cwb, Vb+eps} for queries
__device__ __align__(16) float2 g_F2[TABN]; // (F[i], F[i+1]) pairs
__device__ unsigned int g_sync[2];          // {tab_done, exit}; zero-init

__device__ __forceinline__ float fast_ex2(float x) {
    float y; asm("ex2.approx.f32 %0, %1;" : "=f"(y) : "f"(x)); return y;
}

__device__ __forceinline__ void spin_until(unsigned int* ctr, unsigned int target) {
    while (*((volatile unsigned int*)ctr) < target) __nanosleep(64);
    __threadfence();   // acquire
}

// one head's softmax contribution: ws/se over 64 modules (r precomputed)
__device__ __forceinline__ float eval_head(float x, float r, const float4* __restrict__ ABh)
{
    float mx = -1e30f;
    #pragma unroll 8
    for (int m = 0; m < NM; m++) {
        float4 ab = ABh[m];
        float s = fmaf(r, fmaf(x, ab.x, ab.y), ab.z);
        mx = fmaxf(mx, s);
    }
    float se = 0.f, ws = 0.f;
    #pragma unroll 8
    for (int m = 0; m < NM; m++) {
        float4 ab = ABh[m];
        float s = fmaf(r, fmaf(x, ab.x, ab.y), ab.z);
        float e = fast_ex2(s - mx);
        se += e;
        ws = fmaf(e, ab.w, ws);
    }
    return __fdividef(ws, se);
}

// cold fallback for |x| > 10: full F from global coeffs
__device__ __noinline__ float eval_F_cold(float x, float out_b)
{
    float qa = g_qstat[0], qb2 = g_qstat[1], qc = g_qstat[2];
    float r = rsqrtf(fmaf(x, fmaf(qa, x, qb2), qc));
    float acc = out_b;
    #pragma unroll
    for (int h = 0; h < NHEAD; h++)
        acc += eval_head(x, r, g_AB + h * NM);
    return acc;
}

// =================== kernel 1: prototype pooling (R5 exact) ===================
__global__ __launch_bounds__(POOL_TPB) void pool_kernel(const float* __restrict__ proto) {
    __shared__ float s_red[8];
    const float4* p4 = reinterpret_cast<const float4*>(proto) + (size_t)blockIdx.x * 1280;
    int t = threadIdx.x;
    float4 v0 = p4[t];
    float4 v1 = p4[t + 256];
    float4 v2 = p4[t + 512];
    float4 v3 = p4[t + 768];
    float4 v4 = p4[t + 1024];
    float s0 = (v0.x + v0.y) + (v0.z + v0.w);
    float s1 = (v1.x + v1.y) + (v1.z + v1.w);
    float s2 = (v2.x + v2.y) + (v2.z + v2.w);
    float s3 = (v3.x + v3.y) + (v3.z + v3.w);
    float s4 = (v4.x + v4.y) + (v4.z + v4.w);
    float sum = ((s0 + s1) + (s2 + s3)) + s4;
    #pragma unroll
    for (int off = 16; off; off >>= 1) sum += __shfl_down_sync(0xffffffffu, sum, off);
    if ((t & 31) == 0) s_red[t >> 5] = sum;
    __syncthreads();
    if (t == 0) {
        float v = 0.f;
        #pragma unroll
        for (int w2 = 0; w2 < 8; w2++) v += s_red[w2];
        g_partial[blockIdx.x] = v;
    }
}

// =========== kernel 2: fused table-build + apply ===========
__global__ __launch_bounds__(TA_TPB) void tabapply_kernel(
    const float* __restrict__ coeff, float* __restrict__ out,
    const float* __restrict__ qw, const float* __restrict__ qb,
    const float* __restrict__ qg, const float* __restrict__ qbeta,
    const float* __restrict__ kw, const float* __restrict__ kb,
    const float* __restrict__ kg, const float* __restrict__ kbeta,
    const float* __restrict__ vw, const float* __restrict__ vb,
    const float* __restrict__ vg, const float* __restrict__ vbeta,
    const float* __restrict__ outw, const float* __restrict__ outb,
    const float* __restrict__ gatew, const float* __restrict__ gateb)
{
    __shared__ float  s_pooled[NM];
    __shared__ float  s_stats[15];
    __shared__ float4 s_k[E_DIM];
    __shared__ float4 s_v[E_DIM];
    __shared__ float4 s_q[E_DIM];
    __shared__ float  s_ow[E_DIM];
    __shared__ float4 sAB[NHEAD * NM];

    const int bid = blockIdx.x;
    const int t   = threadIdx.x;
    const int tid = bid * TA_TPB + t;    // one float4 per thread, exact

    const float4* cin = reinterpret_cast<const float4*>(coeff);
    float4* cout = reinterpret_cast<float4*>(out);

    // ---- prologue: issue apply input load immediately (hidden under table build) ----
    float4 xv = cin[tid];
    float gw0 = __ldg(gatew)     * -LOG2E;
    float gw1 = __ldg(gatew + 1) * -LOG2E;
    float gbv = __ldg(gateb)     * -LOG2E;
    float ob  = __ldg(outb);

    // ======================= TABLE role: blocks 0..63 =======================
    if (bid < N_TABB) {
        // stage params (threads 0..127)
        if (t < E_DIM) {
            s_k[t] = make_float4(kw[t], kb[t], kg[t], kbeta[t]);
            s_v[t] = make_float4(vw[t], vb[t], vg[t], vbeta[t]);
            s_q[t] = make_float4(qw[t], qb[t], qg[t], qbeta[t]);
            s_ow[t] = outw[t];
        }
        if (t >= 64 && t < 96) {         // warp 2: moment sums
            int lane = t & 31;
            float acc[15];
            #pragma unroll
            for (int i = 0; i < 15; i++) acc[i] = 0.f;
            #pragma unroll
            for (int rep = 0; rep < 4; rep++) {
                int e = lane + rep * 32;
                float a, b;
                a = qw[e]; b = qb[e];
                acc[0] += a; acc[1] += b; acc[2] += a*a; acc[3] += a*b; acc[4] += b*b;
                a = kw[e]; b = kb[e];
                acc[5] += a; acc[6] += b; acc[7] += a*a; acc[8] += a*b; acc[9] += b*b;
                a = vw[e]; b = vb[e];
                acc[10] += a; acc[11] += b; acc[12] += a*a; acc[13] += a*b; acc[14] += b*b;
            }
            #pragma unroll
            for (int off = 16; off; off >>= 1)
                #pragma unroll
                for (int i = 0; i < 15; i++) acc[i] += __shfl_down_sync(0xffffffffu, acc[i], off);
            if (lane == 0) {
                const float inv = 1.0f / (float)E_DIM;
                #pragma unroll
                for (int gi = 0; gi < 3; gi++) {
                    float mw = acc[gi*5+0] * inv;
                    float mb = acc[gi*5+1] * inv;
                    s_stats[gi*5+0] = mw;
                    s_stats[gi*5+1] = mb;
                    s_stats[gi*5+2] = acc[gi*5+2] * inv - mw*mw;
                    s_stats[gi*5+3] = acc[gi*5+3] * inv - mw*mb;
                    s_stats[gi*5+4] = acc[gi*5+4] * inv - mb*mb;
                }
            }
        }
        if (t < NM) {
            float s = 0.f;
            #pragma unroll
            for (int j = 0; j < 5; j++) s += g_partial[t * 5 + j];
            s_pooled[t] = s * (1.0f / (float)HWSZ);
        }
        __syncthreads();

        float qa  = s_stats[2];
        float qb2 = 2.0f * s_stats[3];
        float qc  = s_stats[4] + LN_EPS;
        if (bid == 0 && t == 0) {
            g_qstat[0] = qa; g_qstat[1] = qb2; g_qstat[2] = qc;
        }

        // coefficients: thread t -> (head, module) entry t (threads 0..255)
        if (t < NHEAD * NM) {
            float mqw = s_stats[0],  mqb = s_stats[1];
            float mkw = s_stats[5],  mkb = s_stats[6];
            float Vkw = s_stats[7],  Ckwb = s_stats[8],  Vkb = s_stats[9];
            float mvw = s_stats[10], mvb = s_stats[11];
            float Vvw = s_stats[12], Cvwb = s_stats[13], Vvb = s_stats[14];
            const float cscale = rsqrtf((float)HDIM) * LOG2E;

            int h = t >> 6, m = t & 63;
            float p = s_pooled[m];
            float rk = rsqrtf(p * p * Vkw + 2.0f * p * Ckwb + Vkb + LN_EPS);
            float rv = rsqrtf(p * p * Vvw + 2.0f * p * Cvwb + Vvb + LN_EPS);

            float a1 = 0.f, a2 = 0.f, a3 = 0.f, w = 0.f;
            #pragma unroll 8
            for (int j = 0; j < HDIM; j++) {
                int e = h * HDIM + j;
                float4 kk = s_k[e];
                float4 vv = s_v[e];
                float4 qq = s_q[e];
                float ke = ((kk.x - mkw) * p + (kk.y - mkb)) * rk * kk.z + kk.w;
                float ve = ((vv.x - mvw) * p + (vv.y - mvb)) * rv * vv.z + vv.w;
                float uq = (qq.x - mqw) * qq.z;
                float tq = (qq.y - mqb) * qq.z;
                a1 = fmaf(uq, ke, a1);
                a2 = fmaf(tq, ke, a2);
                a3 = fmaf(qq.w, ke, a3);
                w  = fmaf(ve, s_ow[e], w);
            }
            float4 out4 = make_float4(a1 * cscale, a2 * cscale, a3 * cscale, w);
            sAB[t] = out4;
            if (bid == 0) g_AB[t] = out4;
        }
        __syncthreads();

        // table nodes: threads 0..255, 2 threads/node (2 heads each), 128 nodes/block
        if (t < 256) {
            const float hstep = (XMAX - XMIN) / (float)(TABN - 1);
            int node = bid * 128 + (t >> 1);    // 64 blocks * 128 = 8192
            int hp   = (t & 1) * 2;             // heads {0,1} or {2,3}
            float x  = XMIN + (float)node * hstep;
            float r  = rsqrtf(fmaf(x, fmaf(qa, x, qb2), qc));
            float part = eval_head(x, r, sAB + (hp << 6))
                       + eval_head(x, r, sAB + ((hp + 1) << 6));
            part += __shfl_xor_sync(0xffffffffu, part, 1);
            if ((t & 1) == 0) {
                float F = part + ob;
                g_F2[node].x = F;
                if (node > 0) g_F2[node - 1].y = F;
            }
        }
        __threadfence();   // release table writes
        __syncthreads();
        if (t == 0) atomicAdd(&g_sync[0], 1u);
    }

    // ---- barrier: wait for full table (backward dep -> deadlock-free) ----
    if (t == 0) spin_until(&g_sync[0], N_TABB);
    __syncthreads();

    // ---- apply: R5's exact hot path (direct gather, gate in-kernel) ----
    const float INVH = (float)(TABN - 1) / (XMAX - XMIN);
    const float BIAS = -XMIN * INVH;

    float xin[4] = {xv.x, xv.y, xv.z, xv.w};
    float2 p[4];
    float fpos[4];
    bool inr[4];
    #pragma unroll
    for (int j = 0; j < 4; j++) {
        float x = xin[j];
        inr[j] = (x >= XMIN) && (x <= XMAX);
        float tpos = fmaf(x, INVH, BIAS);
        int q0 = __float2int_rd(tpos);
        q0 = (q0 < 0) ? 0 : ((q0 > TABN - 2) ? TABN - 2 : q0);
        fpos[j] = tpos - (float)q0;
        p[j] = g_F2[q0];
    }

    float res[4];
    #pragma unroll
    for (int j = 0; j < 4; j++) {
        float x = xin[j];
        float F = inr[j] ? fmaf(fpos[j], p[j].y - p[j].x, p[j].x)
                         : eval_F_cold(x, ob);
        float z = fmaf(gw1, F, fmaf(gw0, x, gbv));
        float g = __fdividef(1.0f, 1.0f + fast_ex2(z));
        res[j] = fmaf(g, F - x, x);
    }
    cout[tid] = make_float4(res[0], res[1], res[2], res[3]);

    // ---- epilogue: last exiting block resets counters (all have passed spin) ----
    __syncthreads();
    if (t == 0) {
        unsigned int old = atomicAdd(&g_sync[1], 1u);
        if (old == (unsigned int)(TA_BLOCKS - 1)) {
            atomicExch(&g_sync[0], 0u);
            atomicExch(&g_sync[1], 0u);
        }
    }
}

// ---------------- launch ----------------
extern "C" void kernel_launch(void* const* d_in, const int* in_sizes, int n_in,
                              void* d_out, int out_size) {
    (void)in_sizes; (void)n_in; (void)out_size;
    const float* coeff = (const float*)d_in[0];
    const float* proto = (const float*)d_in[1];
    const float* qw    = (const float*)d_in[2];
    const float* qb    = (const float*)d_in[3];
    const float* qg    = (const float*)d_in[4];
    const float* qbeta = (const float*)d_in[5];
    const float* kw    = (const float*)d_in[6];
    const float* kb    = (const float*)d_in[7];
    const float* kg    = (const float*)d_in[8];
    const float* kbeta = (const float*)d_in[9];
    const float* vw    = (const float*)d_in[10];
    const float* vb    = (const float*)d_in[11];
    const float* vg    = (const float*)d_in[12];
    const float* vbeta = (const float*)d_in[13];
    const float* outw  = (const float*)d_in[14];
    const float* outb  = (const float*)d_in[15];
    const float* gatew = (const float*)d_in[16];
    const float* gateb = (const float*)d_in[17];
    float* out = (float*)d_out;

    pool_kernel<<<POOL_BLOCKS, POOL_TPB>>>(proto);
    tabapply_kernel<<<TA_BLOCKS, TA_TPB>>>(coeff, out,
                                           qw, qb, qg, qbeta, kw, kb, kg, kbeta,
                                           vw, vb, vg, vbeta, outw, outb,
                                           gatew, gateb);
}

// round 17
// speedup vs baseline: 1.2405x; 1.1799x over previous
#include <cuda_runtime.h>
#include <math.h>

#define NM      64
#define A_DIM   8400
#define E_DIM   128
#define NHEAD   4
#define HDIM    32
#define HWSZ    25600      // 160*160
#define LN_EPS  1e-5f
#define LOG2E   1.4426950408889634f
#define TABN    8192
#define XMIN    -10.0f
#define XMAX    10.0f

#define POOL_BLOCKS 320          // 1280 float4 each, 5 blocks per module (exact)
#define POOL_TPB    256
#define TAB_BLOCKS  64           // 128 nodes per block, 2 threads/node
#define TAB_TPB     256
#define APPLY_BLOCKS 350
#define APPLY_TPB    384         // 350*384 = 134400 float4 exactly

// ---------------- device scratch (no allocation allowed) ----------------
__device__ float        g_partial[POOL_BLOCKS];
__device__ float4       g_AB[NHEAD * NM];   // (A1,A2,A3,W); A* pre-scaled log2e*scale
__device__ float        g_qstat[3];         // {Vw, 2*Cwb, Vb+eps} for queries
__device__ __align__(16) float2 g_F2[TABN]; // (F[i], F[i+1]) pairs

__device__ __forceinline__ float fast_ex2(float x) {
    float y; asm("ex2.approx.f32 %0, %1;" : "=f"(y) : "f"(x)); return y;
}

// one head's softmax contribution: ws/se over 64 modules (r precomputed)
__device__ __forceinline__ float eval_head(float x, float r, const float4* __restrict__ ABh)
{
    float mx = -1e30f;
    #pragma unroll 8
    for (int m = 0; m < NM; m++) {
        float4 ab = ABh[m];
        float s = fmaf(r, fmaf(x, ab.x, ab.y), ab.z);
        mx = fmaxf(mx, s);
    }
    float se = 0.f, ws = 0.f;
    #pragma unroll 8
    for (int m = 0; m < NM; m++) {
        float4 ab = ABh[m];
        float s = fmaf(r, fmaf(x, ab.x, ab.y), ab.z);
        float e = fast_ex2(s - mx);
        se += e;
        ws = fmaf(e, ab.w, ws);
    }
    return __fdividef(ws, se);
}

// cold fallback for |x| > 10: full F from global coeffs
__device__ __noinline__ float eval_F_cold(float x, float out_b)
{
    float qa = g_qstat[0], qb2 = g_qstat[1], qc = g_qstat[2];
    float r = rsqrtf(fmaf(x, fmaf(qa, x, qb2), qc));
    float acc = out_b;
    #pragma unroll
    for (int h = 0; h < NHEAD; h++)
        acc += eval_head(x, r, g_AB + h * NM);
    return acc;
}

// =================== kernel 1: prototype pooling (R5 exact) ===================
__global__ __launch_bounds__(POOL_TPB) void pool_kernel(const float* __restrict__ proto) {
    __shared__ float s_red[8];
    const float4* p4 = reinterpret_cast<const float4*>(proto) + (size_t)blockIdx.x * 1280;
    int t = threadIdx.x;
    float4 v0 = p4[t];
    float4 v1 = p4[t + 256];
    float4 v2 = p4[t + 512];
    float4 v3 = p4[t + 768];
    float4 v4 = p4[t + 1024];
    float s0 = (v0.x + v0.y) + (v0.z + v0.w);
    float s1 = (v1.x + v1.y) + (v1.z + v1.w);
    float s2 = (v2.x + v2.y) + (v2.z + v2.w);
    float s3 = (v3.x + v3.y) + (v3.z + v3.w);
    float s4 = (v4.x + v4.y) + (v4.z + v4.w);
    float sum = ((s0 + s1) + (s2 + s3)) + s4;
    #pragma unroll
    for (int off = 16; off; off >>= 1) sum += __shfl_down_sync(0xffffffffu, sum, off);
    if ((t & 31) == 0) s_red[t >> 5] = sum;
    __syncthreads();
    if (t == 0) {
        float v = 0.f;
        #pragma unroll
        for (int w2 = 0; w2 < 8; w2++) v += s_red[w2];
        g_partial[blockIdx.x] = v;
    }
}

// ============ kernel 2: coefficients + F-table (2 threads/node) ============
__global__ __launch_bounds__(TAB_TPB) void table_kernel(
    const float* __restrict__ qw, const float* __restrict__ qb,
    const float* __restrict__ qg, const float* __restrict__ qbeta,
    const float* __restrict__ kw, const float* __restrict__ kb,
    const float* __restrict__ kg, const float* __restrict__ kbeta,
    const float* __restrict__ vw, const float* __restrict__ vb,
    const float* __restrict__ vg, const float* __restrict__ vbeta,
    const float* __restrict__ outw, const float* __restrict__ outb)
{
    const int tb = blockIdx.x;           // 0..63
    const int t  = threadIdx.x;
    __shared__ float  s_pooled[NM];
    __shared__ float  s_stats[15];
    __shared__ float4 s_k[E_DIM];
    __shared__ float4 s_v[E_DIM];
    __shared__ float4 s_q[E_DIM];
    __shared__ float  s_ow[E_DIM];
    __shared__ float4 sAB[NHEAD * NM];

    // stage params (E = 128)
    if (t < E_DIM) {
        s_k[t] = make_float4(kw[t], kb[t], kg[t], kbeta[t]);
        s_v[t] = make_float4(vw[t], vb[t], vg[t], vbeta[t]);
        s_q[t] = make_float4(qw[t], qb[t], qg[t], qbeta[t]);
        s_ow[t] = outw[t];
    }
    if (t >= 64 && t < 96) {             // warp 2: moment sums
        int lane = t & 31;
        float acc[15];
        #pragma unroll
        for (int i = 0; i < 15; i++) acc[i] = 0.f;
        #pragma unroll
        for (int rep = 0; rep < 4; rep++) {
            int e = lane + rep * 32;
            float a, b;
            a = qw[e]; b = qb[e];
            acc[0] += a; acc[1] += b; acc[2] += a*a; acc[3] += a*b; acc[4] += b*b;
            a = kw[e]; b = kb[e];
            acc[5] += a; acc[6] += b; acc[7] += a*a; acc[8] += a*b; acc[9] += b*b;
            a = vw[e]; b = vb[e];
            acc[10] += a; acc[11] += b; acc[12] += a*a; acc[13] += a*b; acc[14] += b*b;
        }
        #pragma unroll
        for (int off = 16; off; off >>= 1)
            #pragma unroll
            for (int i = 0; i < 15; i++) acc[i] += __shfl_down_sync(0xffffffffu, acc[i], off);
        if (lane == 0) {
            const float inv = 1.0f / (float)E_DIM;
            #pragma unroll
            for (int gi = 0; gi < 3; gi++) {
                float mw = acc[gi*5+0] * inv;
                float mb = acc[gi*5+1] * inv;
                s_stats[gi*5+0] = mw;
                s_stats[gi*5+1] = mb;
                s_stats[gi*5+2] = acc[gi*5+2] * inv - mw*mw;
                s_stats[gi*5+3] = acc[gi*5+3] * inv - mw*mb;
                s_stats[gi*5+4] = acc[gi*5+4] * inv - mb*mb;
            }
        }
    }
    if (t < NM) {
        float s = 0.f;
        #pragma unroll
        for (int j = 0; j < 5; j++) s += g_partial[t * 5 + j];
        s_pooled[t] = s * (1.0f / (float)HWSZ);
    }
    __syncthreads();

    float qa  = s_stats[2];
    float qb2 = 2.0f * s_stats[3];
    float qc  = s_stats[4] + LN_EPS;
    if (tb == 0 && t == 0) {
        g_qstat[0] = qa; g_qstat[1] = qb2; g_qstat[2] = qc;
    }

    // coefficients: thread t -> (head, module) entry t (256 exact)
    {
        float mqw = s_stats[0],  mqb = s_stats[1];
        float mkw = s_stats[5],  mkb = s_stats[6];
        float Vkw = s_stats[7],  Ckwb = s_stats[8],  Vkb = s_stats[9];
        float mvw = s_stats[10], mvb = s_stats[11];
        float Vvw = s_stats[12], Cvwb = s_stats[13], Vvb = s_stats[14];
        const float cscale = rsqrtf((float)HDIM) * LOG2E;

        int h = t >> 6, m = t & 63;
        float p = s_pooled[m];
        float rk = rsqrtf(p * p * Vkw + 2.0f * p * Ckwb + Vkb + LN_EPS);
        float rv = rsqrtf(p * p * Vvw + 2.0f * p * Cvwb + Vvb + LN_EPS);

        float a1 = 0.f, a2 = 0.f, a3 = 0.f, w = 0.f;
        #pragma unroll 8
        for (int j = 0; j < HDIM; j++) {
            int e = h * HDIM + j;
            float4 kk = s_k[e];
            float4 vv = s_v[e];
            float4 qq = s_q[e];
            float ke = ((kk.x - mkw) * p + (kk.y - mkb)) * rk * kk.z + kk.w;
            float ve = ((vv.x - mvw) * p + (vv.y - mvb)) * rv * vv.z + vv.w;
            float uq = (qq.x - mqw) * qq.z;
            float tq = (qq.y - mqb) * qq.z;
            a1 = fmaf(uq, ke, a1);
            a2 = fmaf(tq, ke, a2);
            a3 = fmaf(qq.w, ke, a3);
            w  = fmaf(ve, s_ow[e], w);
        }
        float4 out4 = make_float4(a1 * cscale, a2 * cscale, a3 * cscale, w);
        sAB[t] = out4;
        if (tb == 0) g_AB[t] = out4;
    }
    __syncthreads();

    // F-table: 2 threads/node (2 heads each), shfl-combine; 128 nodes/block
    const float hstep = (XMAX - XMIN) / (float)(TABN - 1);
    float ob = outb[0];
    int node = tb * 128 + (t >> 1);      // 64 blocks * 128 = 8192
    int hp   = (t & 1) * 2;              // heads {0,1} or {2,3}
    float x  = XMIN + (float)node * hstep;
    float r  = rsqrtf(fmaf(x, fmaf(qa, x, qb2), qc));
    float part = eval_head(x, r, sAB + (hp << 6))
               + eval_head(x, r, sAB + ((hp + 1) << 6));
    part += __shfl_xor_sync(0xffffffffu, part, 1);
    if ((t & 1) == 0) {
        float F = part + ob;
        g_F2[node].x = F;
        if (node > 0) g_F2[node - 1].y = F;
    }
}

// =========== kernel 3: apply (R5 exact: direct gather, gate in-kernel) ===========
__global__ __launch_bounds__(APPLY_TPB) void apply_kernel(
    const float* __restrict__ coeff, float* __restrict__ out,
    const float* __restrict__ gatew, const float* __restrict__ gateb,
    const float* __restrict__ outb)
{
    int tid = blockIdx.x * APPLY_TPB + threadIdx.x;   // one float4 each, exact
    const float4* cin = reinterpret_cast<const float4*>(coeff);
    float4* cout = reinterpret_cast<float4*>(out);
    float gw0 = __ldg(gatew)     * -LOG2E;
    float gw1 = __ldg(gatew + 1) * -LOG2E;
    float gbv = __ldg(gateb)     * -LOG2E;
    float ob  = __ldg(outb);

    const float INVH = (float)(TABN - 1) / (XMAX - XMIN);
    const float BIAS = -XMIN * INVH;

    float4 xv = cin[tid];
    float xin[4] = {xv.x, xv.y, xv.z, xv.w};

    // issue all 4 table gathers up front (independent -> MLP)
    float2 p[4];
    float fpos[4];
    bool inr[4];
    #pragma unroll
    for (int j = 0; j < 4; j++) {
        float x = xin[j];
        inr[j] = (x >= XMIN) && (x <= XMAX);
        float tpos = fmaf(x, INVH, BIAS);
        int q0 = __float2int_rd(tpos);
        q0 = (q0 < 0) ? 0 : ((q0 > TABN - 2) ? TABN - 2 : q0);
        fpos[j] = tpos - (float)q0;
        p[j] = g_F2[q0];
    }

    float res[4];
    #pragma unroll
    for (int j = 0; j < 4; j++) {
        float x = xin[j];
        float F = inr[j] ? fmaf(fpos[j], p[j].y - p[j].x, p[j].x)
                         : eval_F_cold(x, ob);
        float z = fmaf(gw1, F, fmaf(gw0, x, gbv));
        float g = __fdividef(1.0f, 1.0f + fast_ex2(z));
        res[j] = fmaf(g, F - x, x);
    }
    cout[tid] = make_float4(res[0], res[1], res[2], res[3]);
}

// ---------------- launch ----------------
extern "C" void kernel_launch(void* const* d_in, const int* in_sizes, int n_in,
                              void* d_out, int out_size) {
    (void)in_sizes; (void)n_in; (void)out_size;
    const float* coeff = (const float*)d_in[0];
    const float* proto = (const float*)d_in[1];
    const float* qw    = (const float*)d_in[2];
    const float* qb    = (const float*)d_in[3];
    const float* qg    = (const float*)d_in[4];
    const float* qbeta = (const float*)d_in[5];
    const float* kw    = (const float*)d_in[6];
    const float* kb    = (const float*)d_in[7];
    const float* kg    = (const float*)d_in[8];
    const float* kbeta = (const float*)d_in[9];
    const float* vw    = (const float*)d_in[10];
    const float* vb    = (const float*)d_in[11];
    const float* vg    = (const float*)d_in[12];
    const float* vbeta = (const float*)d_in[13];
    const float* outw  = (const float*)d_in[14];
    const float* outb  = (const float*)d_in[15];
    const float* gatew = (const float*)d_in[16];
    const float* gateb = (const float*)d_in[17];
    float* out = (float*)d_out;

    pool_kernel<<<POOL_BLOCKS, POOL_TPB>>>(proto);
    table_kernel<<<TAB_BLOCKS, TAB_TPB>>>(qw, qb, qg, qbeta, kw, kb, kg, kbeta,
                                          vw, vb, vg, vbeta, outw, outb);
    apply_kernel<<<APPLY_BLOCKS, APPLY_TPB>>>(coeff, out, gatew, gateb, outb);
}